// round 1
// baseline (speedup 1.0000x reference)
#include <cuda_runtime.h>
#include <cuda_bf16.h>
#include <math.h>

// ---------------- problem constants ----------------
#define NANCH   120000
#define KPRE    2000
#define KPOST   512
#define IOU_THR 0.7f
#define IMG     800.0f
#define SCALE   0.25f
#define CLIPC   4.135166556742356f
#define HF      200
#define WF      200
#define CF      256
#define HW      (HF*WF)          // 40000
#define NWORD   32               // 32 * 64 = 2048 >= 2000
#define SORTN   8192

// ---------------- device scratch (no cudaMalloc allowed) ----------------
__device__ float               g_boxes[NANCH * 4];
__device__ unsigned int        g_hist[65536];
__device__ int                 g_T;
__device__ int                 g_cand_count;
__device__ unsigned long long  g_cand[SORTN];
__device__ float4              g_cand_boxes[2048];
__device__ unsigned long long  g_mask[KPRE * NWORD];   // 512 KB
__device__ unsigned long long  g_keep[NWORD];
__device__ float4              g_fboxes[KPOST];
__device__ int                 g_valid[KPOST];
__device__ float               g_featT[HW * CF];        // (H,W,C) ~41 MB

// ---------------- helpers ----------------
__device__ __forceinline__ unsigned flipf(float v) {
    unsigned u = __float_as_uint(v);
    return (u & 0x80000000u) ? ~u : (u | 0x80000000u);
}

// ---------------- K0: init scratch ----------------
__global__ void init_kernel() {
    int g = blockIdx.x * blockDim.x + threadIdx.x;
    if (g < 65536) g_hist[g] = 0u;
    if (g == 0) g_cand_count = 0;
}

// ---------------- K1: decode boxes + objectness histogram ----------------
__global__ void decode_kernel(const float4* __restrict__ anchors,
                              const float4* __restrict__ deltas,
                              const float*  __restrict__ obj, int N) {
    int i = blockIdx.x * blockDim.x + threadIdx.x;
    if (i >= N) return;
    float4 a = anchors[i];
    float4 d = deltas[i];
    float w  = a.z - a.x, h = a.w - a.y;
    float cx = a.x + 0.5f * w, cy = a.y + 0.5f * h;
    float dw = fminf(d.z, CLIPC), dh = fminf(d.w, CLIPC);
    float pcx = d.x * w + cx, pcy = d.y * h + cy;
    float pw  = expf(dw) * w, ph = expf(dh) * h;
    float bx1 = fminf(fmaxf(pcx - 0.5f * pw, 0.f), IMG);
    float by1 = fminf(fmaxf(pcy - 0.5f * ph, 0.f), IMG);
    float bx2 = fminf(fmaxf(pcx + 0.5f * pw, 0.f), IMG);
    float by2 = fminf(fmaxf(pcy + 0.5f * ph, 0.f), IMG);
    ((float4*)g_boxes)[i] = make_float4(bx1, by1, bx2, by2);

    unsigned u = flipf(obj[i]);
    atomicAdd(&g_hist[u >> 16], 1u);
}

// ---------------- K2: find threshold bin (suffix count >= KPRE) ----------------
__global__ void scan_kernel() {
    __shared__ unsigned csum[256];
    __shared__ unsigned sfx[256];
    int t = threadIdx.x;
    unsigned s = 0;
    #pragma unroll 8
    for (int b = 0; b < 256; b++) s += g_hist[t * 256 + b];
    csum[t] = s;
    __syncthreads();
    if (t == 0) {
        unsigned run = 0;
        for (int i = 255; i >= 0; i--) { sfx[i] = run; run += csum[i]; }
    }
    __syncthreads();
    if (sfx[t] < KPRE && sfx[t] + csum[t] >= KPRE) {
        unsigned cum = sfx[t];
        for (int b = 255; b >= 0; b--) {
            cum += g_hist[t * 256 + b];
            if (cum >= KPRE) { g_T = t * 256 + b; break; }
        }
    }
}

// ---------------- K3: gather candidate keys ----------------
__global__ void gather_kernel(const float* __restrict__ obj, int N) {
    int i = blockIdx.x * blockDim.x + threadIdx.x;
    if (i >= N) return;
    unsigned u = flipf(obj[i]);
    if ((int)(u >> 16) >= g_T) {
        int pos = atomicAdd(&g_cand_count, 1);
        if (pos < SORTN)
            g_cand[pos] = ((unsigned long long)u << 32) |
                          (unsigned long long)(0xFFFFFFFFu - (unsigned)i);
    }
}

// ---------------- K4: one-block bitonic sort (descending), emit top-2000 boxes ----------------
__global__ void sort_kernel() {
    extern __shared__ unsigned long long sk[];
    int tid = threadIdx.x;
    int cnt = g_cand_count; if (cnt > SORTN) cnt = SORTN;
    for (int idx = tid; idx < SORTN; idx += 1024)
        sk[idx] = (idx < cnt) ? g_cand[idx] : 0ull;
    __syncthreads();
    for (int k = 2; k <= SORTN; k <<= 1) {
        for (int j = k >> 1; j > 0; j >>= 1) {
            for (int idx = tid; idx < SORTN; idx += 1024) {
                int ixj = idx ^ j;
                if (ixj > idx) {
                    bool desc = ((idx & k) == 0);
                    unsigned long long a = sk[idx], c = sk[ixj];
                    if ((a < c) == desc) { sk[idx] = c; sk[ixj] = a; }
                }
            }
            __syncthreads();
        }
    }
    for (int t = tid; t < KPRE; t += 1024) {
        unsigned long long key = sk[t];
        unsigned i = ~(unsigned)(key & 0xFFFFFFFFull);
        g_cand_boxes[t] = ((const float4*)g_boxes)[i];
    }
}

// ---------------- K5: 2000x2000 IoU suppression bitmask ----------------
__global__ void iou_kernel() {
    __shared__ float4 cb[64];
    int i  = blockIdx.x * 64 + threadIdx.x;
    int jb = blockIdx.y * 64;
    int j0 = jb + threadIdx.x;
    cb[threadIdx.x] = (j0 < KPRE) ? g_cand_boxes[j0] : make_float4(0, 0, 0, 0);
    __syncthreads();
    if (i >= KPRE) return;
    float4 a = g_cand_boxes[i];
    float Aa = (a.z - a.x) * (a.w - a.y);
    unsigned long long bits = 0ull;
    #pragma unroll 4
    for (int jj = 0; jj < 64; jj++) {
        int j = jb + jj;
        if (j > i && j < KPRE) {
            float4 b = cb[jj];
            float Ab = (b.z - b.x) * (b.w - b.y);
            float lx = fmaxf(a.x, b.x), ly = fmaxf(a.y, b.y);
            float rx = fminf(a.z, b.z), ry = fminf(a.w, b.w);
            float wx = fmaxf(rx - lx, 0.f), wy = fmaxf(ry - ly, 0.f);
            float inter = wx * wy;
            float iou = inter / (Aa + Ab - inter + 1e-6f);
            if (iou > IOU_THR) bits |= (1ull << jj);
        }
    }
    g_mask[i * NWORD + blockIdx.y] = bits;
}

// ---------------- K6: sequential greedy NMS scan (one warp, bitmap in regs) ----------------
__global__ void nms_kernel() {
    int lane = threadIdx.x;
    unsigned long long removed = 0ull;
    for (int i = 0; i < KPRE; i++) {
        unsigned long long m  = g_mask[i * NWORD + lane];
        unsigned long long rw = __shfl_sync(0xffffffffu, removed, i >> 6);
        if (!((rw >> (i & 63)) & 1ull)) removed |= m;
    }
    unsigned long long keep = ~removed;
    if (lane == NWORD - 1) keep &= 0xFFFFull;  // bits for j >= 2000 off
    g_keep[lane] = keep;
}

// ---------------- K7: compact kept boxes into first <=512 slots ----------------
__global__ void compact_kernel() {
    int lane = threadIdx.x;
    for (int s = lane; s < KPOST; s += 32) g_valid[s] = 0;
    __syncwarp();
    unsigned long long kw = g_keep[lane];
    int c = __popcll(kw);
    int pre = c;
    for (int o = 1; o < 32; o <<= 1) {
        int n = __shfl_up_sync(0xffffffffu, pre, o);
        if (lane >= o) pre += n;
    }
    pre -= c;  // exclusive prefix of kept counts
    unsigned long long w = kw; int r = 0;
    while (w) {
        int b = __ffsll((long long)w) - 1;
        int s = pre + r;
        if (s < KPOST) {
            g_valid[s] = 1;
            g_fboxes[s] = g_cand_boxes[lane * 64 + b];
        }
        w &= (w - 1); r++;
    }
}

// ---------------- K8: feature transpose (C,H,W) -> (H*W, C) ----------------
__global__ void transpose_kernel(const float* __restrict__ f) {
    __shared__ float tile[32][33];
    int p = blockIdx.x * 32 + threadIdx.x;
    int c = blockIdx.y * 32 + threadIdx.y;
    tile[threadIdx.y][threadIdx.x] = f[c * HW + p];
    __syncthreads();
    int c2 = blockIdx.y * 32 + threadIdx.x;
    int p2 = blockIdx.x * 32 + threadIdx.y;
    g_featT[p2 * CF + c2] = tile[threadIdx.x][threadIdx.y];
}

// ---------------- K9: ROIAlign (channels-last float4 reads, smem-staged output) ----------------
// dynamic smem: s_out[49*257 (+pad to 12596)] + int4 off[196] + float4 w[196]
#define SOUT_F 12596
#define ROI_SMEM (SOUT_F*4 + 196*16 + 196*16)

__global__ void roi_kernel(float* __restrict__ out) {
    extern __shared__ float sm[];
    float* s_out = sm;
    int4*   s_off = (int4*)(sm + SOUT_F);
    float4* s_w   = (float4*)(s_off + 196);

    int slot = blockIdx.x;
    int tid  = threadIdx.x;
    float* o = out + (size_t)slot * (CF * 49);

    if (!g_valid[slot]) {
        for (int g = tid; g < CF * 49; g += 256) o[g] = 0.0f;
        return;
    }
    float4 b = g_fboxes[slot];
    if (tid < 196) {
        float x1 = b.x * SCALE, y1 = b.y * SCALE;
        float x2 = b.z * SCALE, y2 = b.w * SCALE;
        float rw = fmaxf(x2 - x1, 1.0f), rh = fmaxf(y2 - y1, 1.0f);
        int sy = tid / 14, sx = tid % 14;
        float yv = y1 + ((float)sy + 0.5f) * (rh / 14.0f);
        float xv = x1 + ((float)sx + 0.5f) * (rw / 14.0f);
        yv = fminf(fmaxf(yv, 0.0f), (float)(HF - 1));
        xv = fminf(fmaxf(xv, 0.0f), (float)(WF - 1));
        int y0 = (int)floorf(yv), x0 = (int)floorf(xv);
        int y1i = min(y0 + 1, HF - 1), x1i = min(x0 + 1, WF - 1);
        float ly = yv - (float)y0, lx = xv - (float)x0;
        s_off[tid] = make_int4(y0 * WF + x0, y0 * WF + x1i,
                               y1i * WF + x0, y1i * WF + x1i);
        s_w[tid] = make_float4((1.f - ly) * (1.f - lx), (1.f - ly) * lx,
                               ly * (1.f - lx),          ly * lx);
    }
    __syncthreads();

    int cg = tid & 63;   // channel group: channels 4cg..4cg+3
    int pq = tid >> 6;   // output-pixel phase 0..3
    const float4* ft = (const float4*)g_featT;

    for (int p = pq; p < 49; p += 4) {
        int oy = p / 7, ox = p % 7;
        float ax = 0.f, ay = 0.f, az = 0.f, aw = 0.f;
        #pragma unroll
        for (int a = 0; a < 2; a++) {
            #pragma unroll
            for (int bb = 0; bb < 2; bb++) {
                int s = (2 * oy + a) * 14 + (2 * ox + bb);
                int4   of = s_off[s];
                float4 w  = s_w[s];
                float4 f00 = ft[of.x * 64 + cg];
                float4 f01 = ft[of.y * 64 + cg];
                float4 f10 = ft[of.z * 64 + cg];
                float4 f11 = ft[of.w * 64 + cg];
                ax += w.x * f00.x + w.y * f01.x + w.z * f10.x + w.w * f11.x;
                ay += w.x * f00.y + w.y * f01.y + w.z * f10.y + w.w * f11.y;
                az += w.x * f00.z + w.y * f01.z + w.z * f10.z + w.w * f11.z;
                aw += w.x * f00.w + w.y * f01.w + w.z * f10.w + w.w * f11.w;
            }
        }
        int base = p * 257 + 4 * cg;
        s_out[base + 0] = ax * 0.25f;
        s_out[base + 1] = ay * 0.25f;
        s_out[base + 2] = az * 0.25f;
        s_out[base + 3] = aw * 0.25f;
    }
    __syncthreads();

    // coalesced write-out: out layout is (C,7,7) per slot
    for (int g = tid; g < CF * 49; g += 256) {
        int c = g / 49;
        int p = g - 49 * c;
        o[g] = s_out[p * 257 + c];
    }
}

// ---------------- launcher ----------------
extern "C" void kernel_launch(void* const* d_in, const int* in_sizes, int n_in,
                              void* d_out, int out_size) {
    const float* feature  = (const float*)d_in[0];
    const float* obj      = (const float*)d_in[1];
    const float4* deltas  = (const float4*)d_in[2];
    const float4* anchors = (const float4*)d_in[3];
    float* out = (float*)d_out;
    int N = in_sizes[1];

    cudaFuncSetAttribute(sort_kernel, cudaFuncAttributeMaxDynamicSharedMemorySize, SORTN * 8);
    cudaFuncSetAttribute(roi_kernel,  cudaFuncAttributeMaxDynamicSharedMemorySize, ROI_SMEM);

    init_kernel<<<256, 256>>>();
    decode_kernel<<<(N + 255) / 256, 256>>>(anchors, deltas, obj, N);
    scan_kernel<<<1, 256>>>();
    gather_kernel<<<(N + 255) / 256, 256>>>(obj, N);
    sort_kernel<<<1, 1024, SORTN * 8>>>();
    iou_kernel<<<dim3((KPRE + 63) / 64, (KPRE + 63) / 64), 64>>>();
    nms_kernel<<<1, 32>>>();
    compact_kernel<<<1, 32>>>();
    transpose_kernel<<<dim3(HW / 32, CF / 32), dim3(32, 32)>>>(feature);
    roi_kernel<<<KPOST, 256, ROI_SMEM>>>(out);
}

// round 2
// speedup vs baseline: 1.0264x; 1.0264x over previous
#include <cuda_runtime.h>
#include <cuda_bf16.h>
#include <math.h>

// ---------------- problem constants ----------------
#define NANCH   120000
#define KPRE    2000
#define KPOST   512
#define IMG     800.0f
#define SCALE   0.25f
#define CLIPC   4.135166556742356f
#define HF      200
#define WF      200
#define CF      256
#define HW      (HF*WF)          // 40000
#define NWORD   32               // 32 * 64 = 2048 cols
#define NPAD    2048

// ---------------- device scratch ----------------
__device__ float               g_boxes[NANCH * 4];
__device__ unsigned int        g_hist[65536];
__device__ unsigned int        g_hist2[65536];
__device__ int                 g_T16;
__device__ unsigned int        g_S;        // count strictly above bin T16
__device__ int                 g_cnt1, g_cnt2;
__device__ unsigned long long  g_cand[2048];
__device__ unsigned long long  g_cand2[4096];
__device__ float4              g_cand_boxes[NPAD];
__device__ unsigned long long  g_mask[NPAD * NWORD];
__device__ float4              g_fboxes[KPOST];
__device__ int                 g_valid[KPOST];
__device__ float               g_featT[HW * CF];        // (H*W, C) ~41 MB

// ---------------- helpers ----------------
__device__ __forceinline__ unsigned flipf(float v) {
    unsigned u = __float_as_uint(v);
    return (u & 0x80000000u) ? ~u : (u | 0x80000000u);
}

// ---------------- K0: init ----------------
__global__ void init_kernel() {
    int g = blockIdx.x * 256 + threadIdx.x;
    if (g < 65536) g_hist[g] = 0u;
    else           g_hist2[g - 65536] = 0u;
    if (g == 0) { g_cnt1 = 0; g_cnt2 = 0; }
}

// ---------------- K1: decode + 16-bit histogram ----------------
__global__ void decode_kernel(const float4* __restrict__ anchors,
                              const float4* __restrict__ deltas,
                              const float*  __restrict__ obj, int N) {
    int i = blockIdx.x * blockDim.x + threadIdx.x;
    if (i >= N) return;
    float4 a = anchors[i];
    float4 d = deltas[i];
    float w  = a.z - a.x, h = a.w - a.y;
    float cx = a.x + 0.5f * w, cy = a.y + 0.5f * h;
    float dw = fminf(d.z, CLIPC), dh = fminf(d.w, CLIPC);
    float pcx = d.x * w + cx, pcy = d.y * h + cy;
    float pw  = expf(dw) * w, ph = expf(dh) * h;
    float bx1 = fminf(fmaxf(pcx - 0.5f * pw, 0.f), IMG);
    float by1 = fminf(fmaxf(pcy - 0.5f * ph, 0.f), IMG);
    float bx2 = fminf(fmaxf(pcx + 0.5f * pw, 0.f), IMG);
    float by2 = fminf(fmaxf(pcy + 0.5f * ph, 0.f), IMG);
    ((float4*)g_boxes)[i] = make_float4(bx1, by1, bx2, by2);
    atomicAdd(&g_hist[flipf(obj[i]) >> 16], 1u);
}

// ---------------- K2: locate 16-bit threshold bin ----------------
__global__ void scan_kernel() {
    __shared__ unsigned csum[256];
    __shared__ unsigned sfx[256];
    int t = threadIdx.x;
    unsigned s = 0;
    #pragma unroll 8
    for (int b = 0; b < 256; b++) s += g_hist[t * 256 + b];
    csum[t] = s;
    __syncthreads();
    if (t == 0) {
        unsigned run = 0;
        for (int i = 255; i >= 0; i--) { sfx[i] = run; run += csum[i]; }
    }
    __syncthreads();
    if (sfx[t] < KPRE && sfx[t] + csum[t] >= KPRE) {
        unsigned cum = sfx[t];
        for (int b = 255; b >= 0; b--) {
            unsigned hv = g_hist[t * 256 + b];
            if (cum + hv >= KPRE) { g_T16 = t * 256 + b; g_S = cum; break; }
            cum += hv;
        }
    }
}

// ---------------- K3: gather candidates, low-16 histogram for the bin ----------------
__global__ void gather_kernel(const float* __restrict__ obj, int N) {
    int i = blockIdx.x * blockDim.x + threadIdx.x;
    if (i >= N) return;
    unsigned u = flipf(obj[i]);
    int hi = (int)(u >> 16);
    int T = g_T16;
    if (hi > T) {
        int p = atomicAdd(&g_cnt1, 1);
        if (p < 2048)
            g_cand[p] = ((unsigned long long)u << 32) |
                        (unsigned long long)(0xFFFFFFFFu - (unsigned)i);
    } else if (hi == T) {
        int p = atomicAdd(&g_cnt2, 1);
        if (p < 4096)
            g_cand2[p] = ((unsigned long long)u << 32) |
                         (unsigned long long)(0xFFFFFFFFu - (unsigned)i);
        atomicAdd(&g_hist2[u & 0xFFFFu], 1u);
    }
}

// ---------------- K4: fused (block 0: refine+sort-2048) + (blocks 1..: feature transpose) ----------------
__global__ void sort_transpose_kernel(const float* __restrict__ f) {
    extern __shared__ unsigned char dsm[];
    int tid = threadIdx.x;
    if (blockIdx.x == 0) {
        unsigned long long* sk = (unsigned long long*)dsm;   // 2048 keys
        __shared__ unsigned csum[256];
        __shared__ unsigned sfx[256];
        __shared__ unsigned sT32;
        __shared__ int scount;
        // ---- phase 0: refine threshold to 32 bits ----
        if (tid < 256) {
            unsigned s = 0;
            #pragma unroll 8
            for (int b = 0; b < 256; b++) s += g_hist2[tid * 256 + b];
            csum[tid] = s;
        }
        if (tid == 0) scount = 0;
        __syncthreads();
        if (tid == 0) {
            unsigned run = 0;
            for (int i = 255; i >= 0; i--) { sfx[i] = run; run += csum[i]; }
        }
        __syncthreads();
        unsigned S = g_S;
        unsigned T16 = (unsigned)g_T16;
        if (tid < 256 && S + sfx[tid] < KPRE && S + sfx[tid] + csum[tid] >= KPRE) {
            unsigned cum = S + sfx[tid];
            for (int b = 255; b >= 0; b--) {
                unsigned hv = g_hist2[tid * 256 + b];
                if (cum + hv >= KPRE) { sT32 = (T16 << 16) | (unsigned)(tid * 256 + b); break; }
                cum += hv;
            }
        }
        for (int idx = tid; idx < NPAD; idx += 1024) sk[idx] = 0ull;
        __syncthreads();
        // ---- phase 1: build candidate list ----
        unsigned T32 = sT32;
        int n1 = g_cnt1; if (n1 > 2048) n1 = 2048;
        for (int k = tid; k < n1; k += 1024) {
            int pos = atomicAdd(&scount, 1);
            if (pos < NPAD) sk[pos] = g_cand[k];
        }
        int n2 = g_cnt2; if (n2 > 4096) n2 = 4096;
        for (int k = tid; k < n2; k += 1024) {
            unsigned long long key = g_cand2[k];
            if ((unsigned)(key >> 32) >= T32) {
                int pos = atomicAdd(&scount, 1);
                if (pos < NPAD) sk[pos] = key;
            }
        }
        __syncthreads();
        // ---- phase 2: bitonic sort 2048 descending ----
        for (int k = 2; k <= NPAD; k <<= 1) {
            for (int j = k >> 1; j > 0; j >>= 1) {
                for (int idx = tid; idx < NPAD; idx += 1024) {
                    int ixj = idx ^ j;
                    if (ixj > idx) {
                        bool desc = ((idx & k) == 0);
                        unsigned long long a = sk[idx], c = sk[ixj];
                        if ((a < c) == desc) { sk[idx] = c; sk[ixj] = a; }
                    }
                }
                __syncthreads();
            }
        }
        // ---- phase 3: emit boxes (pad with zero boxes) ----
        for (int t = tid; t < NPAD; t += 1024) {
            if (t < KPRE) {
                unsigned i = ~(unsigned)(sk[t] & 0xFFFFFFFFull);
                g_cand_boxes[t] = ((const float4*)g_boxes)[i];
            } else {
                g_cand_boxes[t] = make_float4(0.f, 0.f, 0.f, 0.f);
            }
        }
    } else {
        // ---- feature transpose: (C,H,W) -> (H*W, C), 32x32 tiles ----
        float (*tile)[33] = (float(*)[33])dsm;
        int t  = blockIdx.x - 1;
        int pb = t % (HW / 32);
        int cb = t / (HW / 32);
        int p0 = pb * 32, c0 = cb * 32;
        int tx = tid & 31, ty = tid >> 5;   // 1024 threads: full 32x32
        tile[ty][tx] = f[(c0 + ty) * HW + p0 + tx];
        __syncthreads();
        g_featT[(size_t)(p0 + ty) * CF + c0 + tx] = tile[tx][ty];
    }
}

// ---------------- K5: IoU suppression bitmask (division-free, upper-tri) ----------------
__global__ void iou_kernel() {
    __shared__ float4 cb[64];
    __shared__ float  cA[64];
    int tid  = threadIdx.x;
    int tx   = tid & 63;
    int isub = tid >> 6;                       // 0..3
    int ib   = blockIdx.x * 4 + isub;          // i-tile 0..31
    int by   = blockIdx.y;                     // j-tile 0..31
    int i    = ib * 64 + tx;
    if (tid < 64) {
        float4 b = g_cand_boxes[by * 64 + tid];
        cb[tid] = b;
        cA[tid] = 0.7f * (b.z - b.x) * (b.w - b.y);
    }
    __syncthreads();
    if (by < ib) { g_mask[i * NWORD + by] = 0ull; return; }
    float4 a = g_cand_boxes[i];
    float c0 = 0.7f * ((a.z - a.x) * (a.w - a.y) + 1e-6f);
    unsigned long long bits = 0ull;
    #pragma unroll 8
    for (int jj = 0; jj < 64; jj++) {
        float4 b = cb[jj];
        float lx = fmaxf(a.x, b.x), ly = fmaxf(a.y, b.y);
        float rx = fminf(a.z, b.z), ry = fminf(a.w, b.w);
        float wx = fmaxf(rx - lx, 0.f), wy = fmaxf(ry - ly, 0.f);
        float inter = wx * wy;
        // iou > 0.7  <=>  1.7*inter > 0.7*(Aa+eps) + 0.7*Ab   (denominator > 0)
        unsigned long long p = (fmaf(1.7f, inter, -(c0 + cA[jj])) > 0.f);
        bits |= p << jj;
    }
    if (by == ib) bits &= (tx == 63) ? 0ull : (~0ull << (tx + 1));
    g_mask[i * NWORD + by] = bits;
}

// ---------------- K6: NMS scan (chunked, early-exit) + compaction ----------------
__global__ void nms_compact_kernel() {
    int lane = threadIdx.x;
    __shared__ unsigned long long diag[64];
    __shared__ unsigned long long skeep[NWORD];
    for (int s = lane; s < KPOST; s += 32) g_valid[s] = 0;
    unsigned long long removed = 0ull;
    int kept_total = 0;
    int c = 0;
    for (; c < NWORD; c++) {
        unsigned long long keepmask = (c == NWORD - 1) ? 0xFFFFull : ~0ull;
        int base = c * 64;
        diag[lane]      = g_mask[(size_t)(base + lane)      * NWORD + c];
        diag[lane + 32] = g_mask[(size_t)(base + lane + 32) * NWORD + c];
        __syncwarp();
        unsigned long long cur  = __shfl_sync(0xffffffffu, removed, c);
        unsigned long long todo = ~cur & keepmask;
        unsigned long long kept = 0ull;
        while (todo) {
            int b = __ffsll((long long)todo) - 1;
            kept |= 1ull << b;
            unsigned long long d = diag[b];
            removed |= g_mask[(size_t)(base + b) * NWORD + lane];
            todo &= ~(d | (1ull << b));
        }
        if (lane == 0) skeep[c] = kept;
        kept_total += __popcll(kept);
        if (kept_total >= KPOST) { c++; break; }
    }
    for (int cc = c + lane; cc < NWORD; cc += 32) skeep[cc] = 0ull;
    __syncwarp();
    // ---- compaction: first <=512 kept, in score order ----
    unsigned long long kw = skeep[lane];
    int cnt = __popcll(kw);
    int pre = cnt;
    #pragma unroll
    for (int o = 1; o < 32; o <<= 1) {
        int n = __shfl_up_sync(0xffffffffu, pre, o);
        if (lane >= o) pre += n;
    }
    pre -= cnt;
    unsigned long long w = kw; int r = 0;
    while (w) {
        int b = __ffsll((long long)w) - 1;
        int s = pre + r;
        if (s < KPOST) {
            g_valid[s] = 1;
            g_fboxes[s] = g_cand_boxes[lane * 64 + b];
        }
        w &= (w - 1); r++;
    }
}

// ---------------- K7: ROIAlign (channels-last float4, smem-staged output) ----------------
#define SOUT_F 12596
#define ROI_SMEM (SOUT_F*4 + 196*16 + 196*16)

__global__ void roi_kernel(float* __restrict__ out) {
    extern __shared__ float sm[];
    float*  s_out = sm;
    int4*   s_off = (int4*)(sm + SOUT_F);
    float4* s_w   = (float4*)(s_off + 196);

    int slot = blockIdx.x;
    int tid  = threadIdx.x;
    float* o = out + (size_t)slot * (CF * 49);

    if (!g_valid[slot]) {
        for (int g = tid; g < CF * 49; g += 256) o[g] = 0.0f;
        return;
    }
    float4 b = g_fboxes[slot];
    if (tid < 196) {
        float x1 = b.x * SCALE, y1 = b.y * SCALE;
        float x2 = b.z * SCALE, y2 = b.w * SCALE;
        float rw = fmaxf(x2 - x1, 1.0f), rh = fmaxf(y2 - y1, 1.0f);
        int sy = tid / 14, sx = tid % 14;
        float yv = y1 + ((float)sy + 0.5f) * (rh / 14.0f);
        float xv = x1 + ((float)sx + 0.5f) * (rw / 14.0f);
        yv = fminf(fmaxf(yv, 0.0f), (float)(HF - 1));
        xv = fminf(fmaxf(xv, 0.0f), (float)(WF - 1));
        int y0 = (int)floorf(yv), x0 = (int)floorf(xv);
        int y1i = min(y0 + 1, HF - 1), x1i = min(x0 + 1, WF - 1);
        float ly = yv - (float)y0, lx = xv - (float)x0;
        s_off[tid] = make_int4(y0 * WF + x0, y0 * WF + x1i,
                               y1i * WF + x0, y1i * WF + x1i);
        s_w[tid] = make_float4((1.f - ly) * (1.f - lx), (1.f - ly) * lx,
                               ly * (1.f - lx),          ly * lx);
    }
    __syncthreads();

    int cg = tid & 63;
    int pq = tid >> 6;
    const float4* ft = (const float4*)g_featT;

    for (int p = pq; p < 49; p += 4) {
        int oy = p / 7, ox = p % 7;
        float ax = 0.f, ay = 0.f, az = 0.f, aw = 0.f;
        #pragma unroll
        for (int a = 0; a < 2; a++) {
            #pragma unroll
            for (int bb = 0; bb < 2; bb++) {
                int s = (2 * oy + a) * 14 + (2 * ox + bb);
                int4   of = s_off[s];
                float4 wv = s_w[s];
                float4 f00 = ft[(size_t)of.x * 64 + cg];
                float4 f01 = ft[(size_t)of.y * 64 + cg];
                float4 f10 = ft[(size_t)of.z * 64 + cg];
                float4 f11 = ft[(size_t)of.w * 64 + cg];
                ax += wv.x * f00.x + wv.y * f01.x + wv.z * f10.x + wv.w * f11.x;
                ay += wv.x * f00.y + wv.y * f01.y + wv.z * f10.y + wv.w * f11.y;
                az += wv.x * f00.z + wv.y * f01.z + wv.z * f10.z + wv.w * f11.z;
                aw += wv.x * f00.w + wv.y * f01.w + wv.z * f10.w + wv.w * f11.w;
            }
        }
        int base = p * 257 + 4 * cg;
        s_out[base + 0] = ax * 0.25f;
        s_out[base + 1] = ay * 0.25f;
        s_out[base + 2] = az * 0.25f;
        s_out[base + 3] = aw * 0.25f;
    }
    __syncthreads();

    for (int g = tid; g < CF * 49; g += 256) {
        int cc = g / 49;
        int p  = g - 49 * cc;
        o[g] = s_out[p * 257 + cc];
    }
}

// ---------------- launcher ----------------
extern "C" void kernel_launch(void* const* d_in, const int* in_sizes, int n_in,
                              void* d_out, int out_size) {
    const float*  feature = (const float*)d_in[0];
    const float*  obj     = (const float*)d_in[1];
    const float4* deltas  = (const float4*)d_in[2];
    const float4* anchors = (const float4*)d_in[3];
    float* out = (float*)d_out;
    int N = in_sizes[1];

    cudaFuncSetAttribute(roi_kernel, cudaFuncAttributeMaxDynamicSharedMemorySize, ROI_SMEM);

    init_kernel<<<512, 256>>>();
    decode_kernel<<<(N + 255) / 256, 256>>>(anchors, deltas, obj, N);
    scan_kernel<<<1, 256>>>();
    gather_kernel<<<(N + 255) / 256, 256>>>(obj, N);
    sort_transpose_kernel<<<1 + (HW / 32) * (CF / 32), 1024, NPAD * 8>>>(feature);
    iou_kernel<<<dim3(8, 32), 256>>>();
    nms_compact_kernel<<<1, 32>>>();
    roi_kernel<<<KPOST, 256, ROI_SMEM>>>(out);
}